// round 16
// baseline (speedup 1.0000x reference)
#include <cuda_runtime.h>
#include <math.h>
#include <stdint.h>

// ---------------- scratch (static __device__, no allocation) ----------------
#define MAXN 65536
#define MAXE 1048576
#define MAXNB 512
#define SCAN_B 512

__device__ __align__(8)  float2 g_degO[MAXN];
__device__ __align__(16) float4 g_degI[MAXN];
__device__ __align__(8)  float2 g_rO[MAXN];
__device__ __align__(8)  float2 g_rI[MAXN];
__device__ int    g_rowptr[MAXN + 1];
__device__ int    g_cursor[MAXN];
__device__ int    g_bsums[MAXNB];
__device__ __align__(16) float4 g_epack[MAXE];              // {src, wf*rO.x, wb*rO.y, -}
__device__ __align__(16) float g_af[(long long)MAXN * 128]; // tf32-rounded
__device__ __align__(16) float g_ab[(long long)MAXN * 128]; // tf32-rounded
__device__ __align__(16) float g_x1[(long long)MAXN * 128];
__device__ __align__(16) float g_x2[(long long)MAXN * 128];
__device__ __align__(16) float g_wt[2 * 3 * 16384];         // pre-rounded weights

// ---------------- tf32 helpers ----------------
__device__ __forceinline__ uint32_t f2tf32(float x) {
    uint32_t r;
    asm("cvt.rna.tf32.f32 %0, %1;" : "=r"(r) : "f"(x));
    return r;
}
__device__ __forceinline__ float f2tf32f(float x) {
    return __uint_as_float(f2tf32(x));
}

__device__ __forceinline__ void mma_tf32(float c[4],
                                         uint32_t a0, uint32_t a1, uint32_t a2, uint32_t a3,
                                         uint32_t b0, uint32_t b1) {
    asm volatile(
        "mma.sync.aligned.m16n8k8.row.col.f32.tf32.tf32.f32 "
        "{%0,%1,%2,%3}, {%4,%5,%6,%7}, {%8,%9}, {%0,%1,%2,%3};"
        : "+f"(c[0]), "+f"(c[1]), "+f"(c[2]), "+f"(c[3])
        : "r"(a0), "r"(a1), "r"(a2), "r"(a3), "r"(b0), "r"(b1));
}

// ---------------- cp.async helpers ----------------
__device__ __forceinline__ void cpa16(void* smem_ptr, const void* gptr, bool valid) {
    uint32_t sa = (uint32_t)__cvta_generic_to_shared(smem_ptr);
    int sz = valid ? 16 : 0;
    asm volatile("cp.async.cg.shared.global [%0], [%1], 16, %2;"
                 :: "r"(sa), "l"(gptr), "r"(sz) : "memory");
}
__device__ __forceinline__ void cpcommit() {
    asm volatile("cp.async.commit_group;" ::: "memory");
}
template <int N>
__device__ __forceinline__ void cpwait() {
    asm volatile("cp.async.wait_group %0;" :: "n"(N) : "memory");
}

// ---------------- prep kernels ----------------

__global__ void zero_wprep_k(const float* __restrict__ W0, const float* __restrict__ W1,
                             const float* __restrict__ W2, int N, int L) {
    int i = blockIdx.x * blockDim.x + threadIdx.x;
    if (i < N) {
        g_degO[i] = make_float2(0.f, 0.f);
        g_degI[i] = make_float4(0.f, 0.f, 0.f, 0.f);
    }
    int wtotal = L * 3 * 16384;
    if (i < wtotal) {
        int layer = i / (3 * 16384);
        int rem = i % (3 * 16384);
        int t = rem / 16384;
        int e = rem % 16384;
        const float* srcp = (t == 0 ? W0 : (t == 1 ? W1 : W2)) + (long long)layer * 16384 + e;
        g_wt[i] = f2tf32f(*srcp);
    }
}

__global__ void edge_prep(const int* __restrict__ ei,
                          const float* __restrict__ theta, int E) {
    int e = blockIdx.x * blockDim.x + threadIdx.x;
    if (e >= E) return;
    int s = ei[e];
    int d = ei[E + e];
    float sn, c;
    sincosf(theta[e], &sn, &c);
    float wf = c * c;
    float wb = sn * sn;
    atomicAdd(&g_degO[s].x, wf);
    atomicAdd(&g_degO[s].y, wb);
    atomicAdd(&g_degI[d].x, wf);
    atomicAdd(&g_degI[d].y, wb);
    atomicAdd(&g_degI[d].z, 1.0f);
}

__global__ void scan1_k(int N) {
    __shared__ int sm[SCAN_B];
    int i = blockIdx.x * SCAN_B + threadIdx.x;
    int v = 0;
    if (i < N) {
        float4 dI = g_degI[i];
        float2 dO = g_degO[i];
        v = (int)dI.z;
        g_rO[i] = make_float2(rsqrtf(fmaxf(dO.x, 1e-30f)), rsqrtf(fmaxf(dO.y, 1e-30f)));
        g_rI[i] = make_float2(rsqrtf(fmaxf(dI.x, 1e-30f)), rsqrtf(fmaxf(dI.y, 1e-30f)));
    }
    sm[threadIdx.x] = v;
    __syncthreads();
    for (int off = 1; off < SCAN_B; off <<= 1) {
        int t = (threadIdx.x >= off) ? sm[threadIdx.x - off] : 0;
        __syncthreads();
        sm[threadIdx.x] += t;
        __syncthreads();
    }
    if (i < N) g_rowptr[i + 1] = sm[threadIdx.x];
    if (threadIdx.x == SCAN_B - 1) g_bsums[blockIdx.x] = sm[SCAN_B - 1];
}

__global__ void __launch_bounds__(MAXNB) scan2_k(int nb) {
    __shared__ int sm[MAXNB];
    int tid = threadIdx.x;
    int v = (tid < nb) ? g_bsums[tid] : 0;
    sm[tid] = v;
    __syncthreads();
    for (int off = 1; off < MAXNB; off <<= 1) {
        int t = (tid >= off) ? sm[tid - off] : 0;
        __syncthreads();
        sm[tid] += t;
        __syncthreads();
    }
    if (tid < nb) g_bsums[tid] = sm[tid] - v;  // exclusive
}

__global__ void scan3_k(int N) {
    int i = blockIdx.x * SCAN_B + threadIdx.x;
    if (i < N) {
        int v = g_rowptr[i + 1] + g_bsums[blockIdx.x];
        g_rowptr[i + 1] = v;
        if (i + 1 < N) g_cursor[i + 1] = v;
    }
    if (i == 0) { g_rowptr[0] = 0; g_cursor[0] = 0; }
}

__global__ void norm_scatter_k(const int* __restrict__ ei,
                               const float* __restrict__ theta, int E) {
    int e = blockIdx.x * blockDim.x + threadIdx.x;
    if (e >= E) return;
    int s = ei[e];
    int d = ei[E + e];
    float sn, c;
    sincosf(theta[e], &sn, &c);
    float2 ro = g_rO[s];
    float wf = c * c * ro.x;
    float wb = sn * sn * ro.y;
    int pos = atomicAdd(&g_cursor[d], 1);
    g_epack[pos] = make_float4(__int_as_float(s), wf, wb, 0.f);
}

// ---------------- aggregation: one warp per node, 8-way pipelined gathers ----
#define AGG_FMA(E, V)                                                      \
    af.x = fmaf(E.y, V.x, af.x); af.y = fmaf(E.y, V.y, af.y);              \
    af.z = fmaf(E.y, V.z, af.z); af.w = fmaf(E.y, V.w, af.w);              \
    ab.x = fmaf(E.z, V.x, ab.x); ab.y = fmaf(E.z, V.y, ab.y);              \
    ab.z = fmaf(E.z, V.z, ab.z); ab.w = fmaf(E.z, V.w, ab.w);

__global__ void __launch_bounds__(256) aggregate_k(const float* __restrict__ xext,
                                                   int xsel, int N) {
    const float* xin = (xsel < 0) ? xext : (xsel == 0 ? g_x1 : g_x2);
    int gw = (blockIdx.x * blockDim.x + threadIdx.x) >> 5;
    int lane = threadIdx.x & 31;
    if (gw >= N) return;
    int beg = g_rowptr[gw], end = g_rowptr[gw + 1];
    float4 af = make_float4(0.f, 0.f, 0.f, 0.f);
    float4 ab = make_float4(0.f, 0.f, 0.f, 0.f);
    const float4* xin4 = reinterpret_cast<const float4*>(xin);
    int p = beg;
    for (; p + 8 <= end; p += 8) {
        float4 e0 = g_epack[p];
        float4 e1 = g_epack[p + 1];
        float4 e2 = g_epack[p + 2];
        float4 e3 = g_epack[p + 3];
        float4 e4 = g_epack[p + 4];
        float4 e5 = g_epack[p + 5];
        float4 e6 = g_epack[p + 6];
        float4 e7 = g_epack[p + 7];
        float4 v0 = xin4[(long long)__float_as_int(e0.x) * 32 + lane];
        float4 v1 = xin4[(long long)__float_as_int(e1.x) * 32 + lane];
        float4 v2 = xin4[(long long)__float_as_int(e2.x) * 32 + lane];
        float4 v3 = xin4[(long long)__float_as_int(e3.x) * 32 + lane];
        float4 v4 = xin4[(long long)__float_as_int(e4.x) * 32 + lane];
        float4 v5 = xin4[(long long)__float_as_int(e5.x) * 32 + lane];
        float4 v6 = xin4[(long long)__float_as_int(e6.x) * 32 + lane];
        float4 v7 = xin4[(long long)__float_as_int(e7.x) * 32 + lane];
        AGG_FMA(e0, v0) AGG_FMA(e1, v1) AGG_FMA(e2, v2) AGG_FMA(e3, v3)
        AGG_FMA(e4, v4) AGG_FMA(e5, v5) AGG_FMA(e6, v6) AGG_FMA(e7, v7)
    }
    for (; p + 4 <= end; p += 4) {
        float4 e0 = g_epack[p];
        float4 e1 = g_epack[p + 1];
        float4 e2 = g_epack[p + 2];
        float4 e3 = g_epack[p + 3];
        float4 v0 = xin4[(long long)__float_as_int(e0.x) * 32 + lane];
        float4 v1 = xin4[(long long)__float_as_int(e1.x) * 32 + lane];
        float4 v2 = xin4[(long long)__float_as_int(e2.x) * 32 + lane];
        float4 v3 = xin4[(long long)__float_as_int(e3.x) * 32 + lane];
        AGG_FMA(e0, v0) AGG_FMA(e1, v1) AGG_FMA(e2, v2) AGG_FMA(e3, v3)
    }
    for (; p < end; ++p) {
        float4 ed = g_epack[p];
        float4 xv = xin4[(long long)__float_as_int(ed.x) * 32 + lane];
        AGG_FMA(ed, xv)
    }
    float2 ri = g_rI[gw];
    float4 afr = make_float4(f2tf32f(af.x * ri.x), f2tf32f(af.y * ri.x),
                             f2tf32f(af.z * ri.x), f2tf32f(af.w * ri.x));
    float4 abr = make_float4(f2tf32f(ab.x * ri.y), f2tf32f(ab.y * ri.y),
                             f2tf32f(ab.z * ri.y), f2tf32f(ab.w * ri.y));
    long long o = (long long)gw * 128 + lane * 4;
    *reinterpret_cast<float4*>(g_af + o) = afr;
    *reinterpret_cast<float4*>(g_ab + o) = abr;
}

// ---------------- fused 3-source tf32 tensor GEMM, cp.async double-buffered ----
#define GEMM3_SMEM_FLOATS 18048
#define GEMM3_SMEM_BYTES (GEMM3_SMEM_FLOATS * 4)
#define AS_IDX(b, r, c) (((b) * 128 + (r)) * 36 + (c))
#define BS_IDX(b, r, c) (9216 + ((b) * 32 + (r)) * 132 + (c))

__global__ void __launch_bounds__(256) gemm3_k(
    const float* __restrict__ xext, int xsel, int layer,
    const float* __restrict__ bias0, const float* __restrict__ bias1, const float* __restrict__ bias2,
    int outsel, int M, int donorm) {

    extern __shared__ float sm[];
    float* sbias = sm + 17664;
    float* red = sm + 17792;

    const float* A2 = (xsel < 0) ? xext : (xsel == 0 ? g_x1 : g_x2);
    const float* Bw = g_wt + (long long)layer * 3 * 16384;
    float* C = (outsel == 0) ? g_x1 : g_x2;

    const int tid = threadIdx.x;
    const int wid = tid >> 5;
    const int lane = tid & 31;
    const int wm = wid & 3;
    const int wn = wid >> 2;
    const int g = lane >> 2;
    const int t = lane & 3;
    const int rowBase = blockIdx.x * 128;

    if (tid < 128) sbias[tid] = bias0[tid] + bias1[tid] + bias2[tid];

    float acc[2][8][4];
#pragma unroll
    for (int i = 0; i < 2; i++)
#pragma unroll
        for (int j = 0; j < 8; j++)
#pragma unroll
            for (int q = 0; q < 4; q++) acc[i][j][q] = 0.f;

    const float* Alist[3] = { g_af, g_ab, A2 };

    auto issue = [&](int c, int buf) {
        const float* A = Alist[c >> 2];
        const float* B = Bw + (long long)(c >> 2) * 16384;
        const int ks = (c & 3) * 32;
#pragma unroll
        for (int l = 0; l < 4; l++) {
            int idx = tid + l * 256;
            int ar = idx >> 3;
            int ac = (idx & 7) * 4;
            int gr = rowBase + ar;
            bool ok = (gr < M);
            const float* src = A + (long long)(ok ? gr : 0) * 128 + ks + ac;
            cpa16(&sm[AS_IDX(buf, ar, ac)], src, ok);
        }
#pragma unroll
        for (int l = 0; l < 4; l++) {
            int idx = tid + l * 256;
            int br = idx >> 5;
            int bc = (idx & 31) * 4;
            cpa16(&sm[BS_IDX(buf, br, bc)], B + (ks + br) * 128 + bc, true);
        }
    };

    issue(0, 0);
    cpcommit();

#pragma unroll 1
    for (int c = 0; c < 12; c++) {
        if (c + 1 < 12) {
            issue(c + 1, (c + 1) & 1);
            cpcommit();
            cpwait<1>();
        } else {
            cpwait<0>();
        }
        __syncthreads();

        const int buf = c & 1;
        const bool needcvt = (c >> 2) == 2;

#pragma unroll
        for (int kk = 0; kk < 4; kk++) {
            const int kb = kk * 8;
            uint32_t a[2][4];
#pragma unroll
            for (int mf = 0; mf < 2; mf++) {
                int r0 = wm * 32 + mf * 16 + g;
                float v0 = sm[AS_IDX(buf, r0, kb + t)];
                float v1 = sm[AS_IDX(buf, r0 + 8, kb + t)];
                float v2 = sm[AS_IDX(buf, r0, kb + t + 4)];
                float v3 = sm[AS_IDX(buf, r0 + 8, kb + t + 4)];
                if (needcvt) {
                    a[mf][0] = f2tf32(v0); a[mf][1] = f2tf32(v1);
                    a[mf][2] = f2tf32(v2); a[mf][3] = f2tf32(v3);
                } else {
                    a[mf][0] = __float_as_uint(v0); a[mf][1] = __float_as_uint(v1);
                    a[mf][2] = __float_as_uint(v2); a[mf][3] = __float_as_uint(v3);
                }
            }
#pragma unroll
            for (int j = 0; j < 8; j++) {
                int n0 = wn * 64 + j * 8 + g;
                uint32_t b0 = __float_as_uint(sm[BS_IDX(buf, kb + t, n0)]);
                uint32_t b1 = __float_as_uint(sm[BS_IDX(buf, kb + t + 4, n0)]);
                mma_tf32(acc[0][j], a[0][0], a[0][1], a[0][2], a[0][3], b0, b1);
                mma_tf32(acc[1][j], a[1][0], a[1][1], a[1][2], a[1][3], b0, b1);
            }
        }
        __syncthreads();
    }

    if (donorm) {
        float ss[2][2] = { {0.f, 0.f}, {0.f, 0.f} };
#pragma unroll
        for (int mf = 0; mf < 2; mf++)
#pragma unroll
            for (int j = 0; j < 8; j++) {
                int n0 = wn * 64 + j * 8 + 2 * t;
                float b0 = sbias[n0], b1 = sbias[n0 + 1];
                float v0 = acc[mf][j][0] + b0; v0 = v0 > 0.f ? v0 : 0.f;
                float v1 = acc[mf][j][1] + b1; v1 = v1 > 0.f ? v1 : 0.f;
                float v2 = acc[mf][j][2] + b0; v2 = v2 > 0.f ? v2 : 0.f;
                float v3 = acc[mf][j][3] + b1; v3 = v3 > 0.f ? v3 : 0.f;
                acc[mf][j][0] = v0; acc[mf][j][1] = v1;
                acc[mf][j][2] = v2; acc[mf][j][3] = v3;
                ss[mf][0] = fmaf(v0, v0, fmaf(v1, v1, ss[mf][0]));
                ss[mf][1] = fmaf(v2, v2, fmaf(v3, v3, ss[mf][1]));
            }
#pragma unroll
        for (int mf = 0; mf < 2; mf++)
#pragma unroll
            for (int rp = 0; rp < 2; rp++) {
                float s = ss[mf][rp];
                s += __shfl_xor_sync(0xffffffffu, s, 1);
                s += __shfl_xor_sync(0xffffffffu, s, 2);
                ss[mf][rp] = s;
            }
        if (t == 0) {
#pragma unroll
            for (int mf = 0; mf < 2; mf++) {
                red[(wm * 32 + mf * 16 + g) * 2 + wn] = ss[mf][0];
                red[(wm * 32 + mf * 16 + g + 8) * 2 + wn] = ss[mf][1];
            }
        }
        __syncthreads();
#pragma unroll
        for (int mf = 0; mf < 2; mf++) {
            int r0 = wm * 32 + mf * 16 + g;
            float s0 = red[r0 * 2] + red[r0 * 2 + 1];
            float s1 = red[(r0 + 8) * 2] + red[(r0 + 8) * 2 + 1];
            float inv0 = 1.f / fmaxf(sqrtf(s0), 1e-12f);
            float inv1 = 1.f / fmaxf(sqrtf(s1), 1e-12f);
#pragma unroll
            for (int j = 0; j < 8; j++) {
                acc[mf][j][0] *= inv0; acc[mf][j][1] *= inv0;
                acc[mf][j][2] *= inv1; acc[mf][j][3] *= inv1;
            }
        }
    } else {
#pragma unroll
        for (int mf = 0; mf < 2; mf++)
#pragma unroll
            for (int j = 0; j < 8; j++) {
                int n0 = wn * 64 + j * 8 + 2 * t;
                float b0 = sbias[n0], b1 = sbias[n0 + 1];
                acc[mf][j][0] += b0; acc[mf][j][1] += b1;
                acc[mf][j][2] += b0; acc[mf][j][3] += b1;
            }
    }

#pragma unroll
    for (int mf = 0; mf < 2; mf++) {
        int r0 = rowBase + wm * 32 + mf * 16 + g;
        int r1 = r0 + 8;
#pragma unroll
        for (int j = 0; j < 8; j++) {
            int n0 = wn * 64 + j * 8 + 2 * t;
            if (r0 < M) {
                float2 v = make_float2(acc[mf][j][0], acc[mf][j][1]);
                *reinterpret_cast<float2*>(C + (long long)r0 * 128 + n0) = v;
            }
            if (r1 < M) {
                float2 v = make_float2(acc[mf][j][2], acc[mf][j][3]);
                *reinterpret_cast<float2*>(C + (long long)r1 * 128 + n0) = v;
            }
        }
    }
}

// ---------------- readout via tf32 MMA: out[M,64] = h @ W_ro + b_ro ----------
#define RO_SMEM_FLOATS 13568
#define RO_SMEM_BYTES (RO_SMEM_FLOATS * 4)
#define ROA_IDX(b, r, c) (((b) * 128 + (r)) * 36 + (c))
#define ROB_IDX(b, r, c) (9216 + ((b) * 32 + (r)) * 68 + (c))

__global__ void __launch_bounds__(256) readout_mma_k(
    int xsel, const float* __restrict__ Wro, const float* __restrict__ bro,
    float* __restrict__ out, int M) {

    extern __shared__ float sm[];
    const float* A = (xsel == 0) ? g_x1 : g_x2;

    const int tid = threadIdx.x;
    const int wid = tid >> 5;
    const int lane = tid & 31;
    const int wm = wid & 3;
    const int wn = wid >> 2;
    const int g = lane >> 2;
    const int t = lane & 3;
    const int rowBase = blockIdx.x * 128;

    float acc[2][4][4];
#pragma unroll
    for (int i = 0; i < 2; i++)
#pragma unroll
        for (int j = 0; j < 4; j++)
#pragma unroll
            for (int q = 0; q < 4; q++) acc[i][j][q] = 0.f;

    auto issue = [&](int c, int buf) {
        const int ks = c * 32;
#pragma unroll
        for (int l = 0; l < 4; l++) {
            int idx = tid + l * 256;
            int ar = idx >> 3;
            int ac = (idx & 7) * 4;
            int gr = rowBase + ar;
            bool ok = (gr < M);
            const float* src = A + (long long)(ok ? gr : 0) * 128 + ks + ac;
            cpa16(&sm[ROA_IDX(buf, ar, ac)], src, ok);
        }
#pragma unroll
        for (int l = 0; l < 2; l++) {
            int idx = tid + l * 256;
            int br = idx >> 4;
            int bc = (idx & 15) * 4;
            cpa16(&sm[ROB_IDX(buf, br, bc)], Wro + (ks + br) * 64 + bc, true);
        }
    };

    issue(0, 0);
    cpcommit();

#pragma unroll 1
    for (int c = 0; c < 4; c++) {
        if (c + 1 < 4) {
            issue(c + 1, (c + 1) & 1);
            cpcommit();
            cpwait<1>();
        } else {
            cpwait<0>();
        }
        __syncthreads();

        const int buf = c & 1;

#pragma unroll
        for (int kk = 0; kk < 4; kk++) {
            const int kb = kk * 8;
            uint32_t a[2][4];
#pragma unroll
            for (int mf = 0; mf < 2; mf++) {
                int r0 = wm * 32 + mf * 16 + g;
                a[mf][0] = f2tf32(sm[ROA_IDX(buf, r0, kb + t)]);
                a[mf][1] = f2tf32(sm[ROA_IDX(buf, r0 + 8, kb + t)]);
                a[mf][2] = f2tf32(sm[ROA_IDX(buf, r0, kb + t + 4)]);
                a[mf][3] = f2tf32(sm[ROA_IDX(buf, r0 + 8, kb + t + 4)]);
            }
#pragma unroll
            for (int j = 0; j < 4; j++) {
                int n0 = wn * 32 + j * 8 + g;
                uint32_t b0 = f2tf32(sm[ROB_IDX(buf, kb + t, n0)]);
                uint32_t b1 = f2tf32(sm[ROB_IDX(buf, kb + t + 4, n0)]);
                mma_tf32(acc[0][j], a[0][0], a[0][1], a[0][2], a[0][3], b0, b1);
                mma_tf32(acc[1][j], a[1][0], a[1][1], a[1][2], a[1][3], b0, b1);
            }
        }
        __syncthreads();
    }

#pragma unroll
    for (int mf = 0; mf < 2; mf++) {
        int r0 = rowBase + wm * 32 + mf * 16 + g;
        int r1 = r0 + 8;
#pragma unroll
        for (int j = 0; j < 4; j++) {
            int n0 = wn * 32 + j * 8 + 2 * t;
            float b0 = bro[n0], b1 = bro[n0 + 1];
            if (r0 < M) {
                float2 v = make_float2(acc[mf][j][0] + b0, acc[mf][j][1] + b1);
                *reinterpret_cast<float2*>(out + (long long)r0 * 64 + n0) = v;
            }
            if (r1 < M) {
                float2 v = make_float2(acc[mf][j][2] + b0, acc[mf][j][3] + b1);
                *reinterpret_cast<float2*>(out + (long long)r1 * 64 + n0) = v;
            }
        }
    }
}

// ---------------- launch ----------------
extern "C" void kernel_launch(void* const* d_in, const int* in_sizes, int n_in,
                              void* d_out, int out_size) {
    const float* x          = (const float*)d_in[0];
    const int* ei           = (const int*)d_in[1];
    const float* theta      = (const float*)d_in[2];
    const float* Ws2d       = (const float*)d_in[3];
    const float* Wd2s       = (const float*)d_in[4];
    const float* Wself      = (const float*)d_in[5];
    const float* bs2d       = (const float*)d_in[6];
    const float* bd2s       = (const float*)d_in[7];
    const float* bself      = (const float*)d_in[8];
    const float* W_ro       = (const float*)d_in[9];
    const float* b_ro       = (const float*)d_in[10];
    float* out = (float*)d_out;

    int N = in_sizes[0] / 128;
    int E = in_sizes[2];
    int L = in_sizes[3] / (128 * 128);

    cudaFuncSetAttribute(gemm3_k, cudaFuncAttributeMaxDynamicSharedMemorySize,
                         GEMM3_SMEM_BYTES);
    cudaFuncSetAttribute(readout_mma_k, cudaFuncAttributeMaxDynamicSharedMemorySize,
                         RO_SMEM_BYTES);

    int nb = (N + SCAN_B - 1) / SCAN_B;
    int prepCnt = (N > L * 3 * 16384) ? N : L * 3 * 16384;

    zero_wprep_k<<<(prepCnt + 255) / 256, 256>>>(Ws2d, Wd2s, Wself, N, L);
    edge_prep<<<(E + 255) / 256, 256>>>(ei, theta, E);
    scan1_k<<<nb, SCAN_B>>>(N);
    scan2_k<<<1, MAXNB>>>(nb);
    scan3_k<<<nb, SCAN_B>>>(N);
    norm_scatter_k<<<(E + 255) / 256, 256>>>(ei, theta, E);

    int gemmGrid = (N + 127) / 128;
    int aggGrid = (N * 32 + 255) / 256;

    for (int i = 0; i < L; i++) {
        int xsel = (i == 0) ? -1 : ((i - 1) & 1);
        int outsel = i & 1;
        aggregate_k<<<aggGrid, 256>>>(x, xsel, N);
        gemm3_k<<<gemmGrid, 256, GEMM3_SMEM_BYTES>>>(
            x, xsel, i,
            bs2d + i * 128, bd2s + i * 128, bself + i * 128,
            outsel, N, (i != L - 1) ? 1 : 0);
    }
    readout_mma_k<<<gemmGrid, 256, RO_SMEM_BYTES>>>((L - 1) & 1, W_ro, b_ro, out, N);
}

// round 17
// speedup vs baseline: 1.1467x; 1.1467x over previous
#include <cuda_runtime.h>
#include <cuda_fp16.h>
#include <math.h>
#include <stdint.h>

// ---------------- scratch (static __device__, no allocation) ----------------
#define MAXN 65536
#define MAXE 1048576
#define MAXNB 512
#define SCAN_B 512

__device__ __align__(8)  float2 g_degO[MAXN];
__device__ __align__(16) float4 g_degI[MAXN];
__device__ __align__(8)  float2 g_rO[MAXN];
__device__ __align__(8)  float2 g_rI[MAXN];
__device__ int    g_rowptr[MAXN + 1];
__device__ int    g_cursor[MAXN];
__device__ int    g_bsums[MAXNB];
__device__ __align__(16) float4 g_epack[MAXE];               // {src, wf*rO.x, wb*rO.y, -}
__device__ __align__(16) __half g_af[(long long)MAXN * 128]; // fp16 (gemm operand)
__device__ __align__(16) __half g_ab[(long long)MAXN * 128]; // fp16 (gemm operand)
__device__ __align__(16) float g_x1[(long long)MAXN * 128];  // fp32 activations (aggregate)
__device__ __align__(16) float g_x2[(long long)MAXN * 128];
__device__ __align__(16) __half g_xh0[(long long)MAXN * 128]; // fp16 x (gemm operand)
__device__ __align__(16) __half g_xh1[(long long)MAXN * 128]; // fp16 activations
__device__ __align__(16) __half g_xh2[(long long)MAXN * 128];
__device__ __align__(8) __half2 g_wt2[2 * 3 * 8192];          // k-pair-packed weights
__device__ __align__(8) __half2 g_wro2[4096];                 // k-pair-packed W_ro

// ---------------- mma helpers ----------------
__device__ __forceinline__ void mma_f16(float c[4],
                                        uint32_t a0, uint32_t a1, uint32_t a2, uint32_t a3,
                                        uint32_t b0, uint32_t b1) {
    asm volatile(
        "mma.sync.aligned.m16n8k16.row.col.f32.f16.f16.f32 "
        "{%0,%1,%2,%3}, {%4,%5,%6,%7}, {%8,%9}, {%0,%1,%2,%3};"
        : "+f"(c[0]), "+f"(c[1]), "+f"(c[2]), "+f"(c[3])
        : "r"(a0), "r"(a1), "r"(a2), "r"(a3), "r"(b0), "r"(b1));
}

// ---------------- cp.async helpers ----------------
__device__ __forceinline__ void cpa16(void* smem_ptr, const void* gptr, bool valid) {
    uint32_t sa = (uint32_t)__cvta_generic_to_shared(smem_ptr);
    int sz = valid ? 16 : 0;
    asm volatile("cp.async.cg.shared.global [%0], [%1], 16, %2;"
                 :: "r"(sa), "l"(gptr), "r"(sz) : "memory");
}
__device__ __forceinline__ void cpcommit() {
    asm volatile("cp.async.commit_group;" ::: "memory");
}
template <int N>
__device__ __forceinline__ void cpwait() {
    asm volatile("cp.async.wait_group %0;" :: "n"(N) : "memory");
}

// ---------------- prep kernels ----------------

// zero degrees + pack weights/W_ro to half2 k-pairs + half mirror of x
__global__ void zero_wprep_k(const float* __restrict__ x,
                             const float* __restrict__ W0, const float* __restrict__ W1,
                             const float* __restrict__ W2, const float* __restrict__ Wro,
                             int N, int L) {
    int i = blockIdx.x * blockDim.x + threadIdx.x;
    if (i < N) {
        g_degO[i] = make_float2(0.f, 0.f);
        g_degI[i] = make_float4(0.f, 0.f, 0.f, 0.f);
    }
    int wtotal = L * 3 * 8192;
    if (i < wtotal) {
        int layer = i / (3 * 8192);
        int rem = i % (3 * 8192);
        int t = rem / 8192;
        int e = rem % 8192;
        int kp = e >> 7;
        int n = e & 127;
        const float* Wsrc = (t == 0 ? W0 : (t == 1 ? W1 : W2)) + (long long)layer * 16384;
        g_wt2[i] = __floats2half2_rn(Wsrc[(2 * kp) * 128 + n], Wsrc[(2 * kp + 1) * 128 + n]);
    }
    if (i < 4096) {
        int kp = i >> 6;
        int n = i & 63;
        g_wro2[i] = __floats2half2_rn(Wro[(2 * kp) * 64 + n], Wro[(2 * kp + 1) * 64 + n]);
    }
    long long xtotal = (long long)N * 128;
    if (i < xtotal) g_xh0[i] = __float2half_rn(x[i]);
}

__global__ void edge_prep(const int* __restrict__ ei,
                          const float* __restrict__ theta, int E) {
    int e = blockIdx.x * blockDim.x + threadIdx.x;
    if (e >= E) return;
    int s = ei[e];
    int d = ei[E + e];
    float sn, c;
    sincosf(theta[e], &sn, &c);
    float wf = c * c;
    float wb = sn * sn;
    atomicAdd(&g_degO[s].x, wf);
    atomicAdd(&g_degO[s].y, wb);
    atomicAdd(&g_degI[d].x, wf);
    atomicAdd(&g_degI[d].y, wb);
    atomicAdd(&g_degI[d].z, 1.0f);
}

__global__ void scan1_k(int N) {
    __shared__ int sm[SCAN_B];
    int i = blockIdx.x * SCAN_B + threadIdx.x;
    int v = 0;
    if (i < N) {
        float4 dI = g_degI[i];
        float2 dO = g_degO[i];
        v = (int)dI.z;
        g_rO[i] = make_float2(rsqrtf(fmaxf(dO.x, 1e-30f)), rsqrtf(fmaxf(dO.y, 1e-30f)));
        g_rI[i] = make_float2(rsqrtf(fmaxf(dI.x, 1e-30f)), rsqrtf(fmaxf(dI.y, 1e-30f)));
    }
    sm[threadIdx.x] = v;
    __syncthreads();
    for (int off = 1; off < SCAN_B; off <<= 1) {
        int t = (threadIdx.x >= off) ? sm[threadIdx.x - off] : 0;
        __syncthreads();
        sm[threadIdx.x] += t;
        __syncthreads();
    }
    if (i < N) g_rowptr[i + 1] = sm[threadIdx.x];
    if (threadIdx.x == SCAN_B - 1) g_bsums[blockIdx.x] = sm[SCAN_B - 1];
}

__global__ void __launch_bounds__(MAXNB) scan2_k(int nb) {
    __shared__ int sm[MAXNB];
    int tid = threadIdx.x;
    int v = (tid < nb) ? g_bsums[tid] : 0;
    sm[tid] = v;
    __syncthreads();
    for (int off = 1; off < MAXNB; off <<= 1) {
        int t = (tid >= off) ? sm[tid - off] : 0;
        __syncthreads();
        sm[tid] += t;
        __syncthreads();
    }
    if (tid < nb) g_bsums[tid] = sm[tid] - v;  // exclusive
}

__global__ void scan3_k(int N) {
    int i = blockIdx.x * SCAN_B + threadIdx.x;
    if (i < N) {
        int v = g_rowptr[i + 1] + g_bsums[blockIdx.x];
        g_rowptr[i + 1] = v;
        if (i + 1 < N) g_cursor[i + 1] = v;
    }
    if (i == 0) { g_rowptr[0] = 0; g_cursor[0] = 0; }
}

__global__ void norm_scatter_k(const int* __restrict__ ei,
                               const float* __restrict__ theta, int E) {
    int e = blockIdx.x * blockDim.x + threadIdx.x;
    if (e >= E) return;
    int s = ei[e];
    int d = ei[E + e];
    float sn, c;
    sincosf(theta[e], &sn, &c);
    float2 ro = g_rO[s];
    float wf = c * c * ro.x;
    float wb = sn * sn * ro.y;
    int pos = atomicAdd(&g_cursor[d], 1);
    g_epack[pos] = make_float4(__int_as_float(s), wf, wb, 0.f);
}

// ---------------- aggregation: one warp per node, 4-way pipelined gathers ----
#define AGG_FMA(E, V)                                                      \
    af.x = fmaf(E.y, V.x, af.x); af.y = fmaf(E.y, V.y, af.y);              \
    af.z = fmaf(E.y, V.z, af.z); af.w = fmaf(E.y, V.w, af.w);              \
    ab.x = fmaf(E.z, V.x, ab.x); ab.y = fmaf(E.z, V.y, ab.y);              \
    ab.z = fmaf(E.z, V.z, ab.z); ab.w = fmaf(E.z, V.w, ab.w);

__global__ void __launch_bounds__(256) aggregate_k(const float* __restrict__ xext,
                                                   int xsel, int N) {
    const float* xin = (xsel < 0) ? xext : (xsel == 0 ? g_x1 : g_x2);
    int gw = (blockIdx.x * blockDim.x + threadIdx.x) >> 5;
    int lane = threadIdx.x & 31;
    if (gw >= N) return;
    int beg = g_rowptr[gw], end = g_rowptr[gw + 1];
    float4 af = make_float4(0.f, 0.f, 0.f, 0.f);
    float4 ab = make_float4(0.f, 0.f, 0.f, 0.f);
    const float4* xin4 = reinterpret_cast<const float4*>(xin);
    int p = beg;
    for (; p + 4 <= end; p += 4) {
        float4 e0 = g_epack[p];
        float4 e1 = g_epack[p + 1];
        float4 e2 = g_epack[p + 2];
        float4 e3 = g_epack[p + 3];
        float4 v0 = xin4[(long long)__float_as_int(e0.x) * 32 + lane];
        float4 v1 = xin4[(long long)__float_as_int(e1.x) * 32 + lane];
        float4 v2 = xin4[(long long)__float_as_int(e2.x) * 32 + lane];
        float4 v3 = xin4[(long long)__float_as_int(e3.x) * 32 + lane];
        AGG_FMA(e0, v0) AGG_FMA(e1, v1) AGG_FMA(e2, v2) AGG_FMA(e3, v3)
    }
    for (; p < end; ++p) {
        float4 ed = g_epack[p];
        float4 xv = xin4[(long long)__float_as_int(ed.x) * 32 + lane];
        AGG_FMA(ed, xv)
    }
    float2 ri = g_rI[gw];
    __half2 hf0 = __floats2half2_rn(af.x * ri.x, af.y * ri.x);
    __half2 hf1 = __floats2half2_rn(af.z * ri.x, af.w * ri.x);
    __half2 hb0 = __floats2half2_rn(ab.x * ri.y, ab.y * ri.y);
    __half2 hb1 = __floats2half2_rn(ab.z * ri.y, ab.w * ri.y);
    long long o = (long long)gw * 128 + lane * 4;
    uint2 uf = make_uint2(*reinterpret_cast<uint32_t*>(&hf0), *reinterpret_cast<uint32_t*>(&hf1));
    uint2 ub = make_uint2(*reinterpret_cast<uint32_t*>(&hb0), *reinterpret_cast<uint32_t*>(&hb1));
    *reinterpret_cast<uint2*>(g_af + o) = uf;
    *reinterpret_cast<uint2*>(g_ab + o) = ub;
}

// ---------------- fused 3-source fp16 tensor GEMM, cp.async double-buffered ----
// A tiles: half [128][40] per buffer; B tiles: half2 k-pairs [16][132] per buffer
#define G3_AS(b, r, c) (((b) * 128 + (r)) * 40 + (c))      // halfs
#define G3_BS(b, k2, n) (((b) * 16 + (k2)) * 132 + (n))    // half2 units
#define GEMM3H_SMEM_BYTES 38912
// layout: As halfs @0 (20480B), Bs half2 @20480 (16896B), sbias @37376, red @37888

__global__ void __launch_bounds__(256) gemm3_k(
    int xsel, int layer,
    const float* __restrict__ bias0, const float* __restrict__ bias1, const float* __restrict__ bias2,
    int outsel, int M, int donorm) {

    extern __shared__ char smc[];
    __half* As = reinterpret_cast<__half*>(smc);
    __half2* Bs = reinterpret_cast<__half2*>(smc + 20480);
    float* sbias = reinterpret_cast<float*>(smc + 37376);
    float* red = reinterpret_cast<float*>(smc + 37888);

    const __half* A2 = (xsel < 0) ? g_xh0 : (xsel == 0 ? g_xh1 : g_xh2);
    const __half2* Bw = g_wt2 + (long long)layer * 3 * 8192;
    float* Cf = (outsel == 0) ? g_x1 : g_x2;
    __half2* Ch = reinterpret_cast<__half2*>((outsel == 0) ? g_xh1 : g_xh2);

    const int tid = threadIdx.x;
    const int wid = tid >> 5;
    const int lane = tid & 31;
    const int wm = wid & 3;
    const int wn = wid >> 2;
    const int g = lane >> 2;
    const int t = lane & 3;
    const int rowBase = blockIdx.x * 128;

    if (tid < 128) sbias[tid] = bias0[tid] + bias1[tid] + bias2[tid];

    float acc[2][8][4];
#pragma unroll
    for (int i = 0; i < 2; i++)
#pragma unroll
        for (int j = 0; j < 8; j++)
#pragma unroll
            for (int q = 0; q < 4; q++) acc[i][j][q] = 0.f;

    const __half* Alist[3] = { g_af, g_ab, A2 };

    auto issue = [&](int c, int buf) {
        const __half* A = Alist[c >> 2];
        const __half2* B = Bw + (long long)(c >> 2) * 8192 + (c & 3) * 16 * 128;
        const int ks = (c & 3) * 32;   // halfs
        // A chunk: 128 rows x 32 halfs (64B/row -> 4x16B), 512 loads
#pragma unroll
        for (int l = 0; l < 2; l++) {
            int idx = tid + l * 256;
            int ar = idx >> 2;
            int ac = idx & 3;
            int gr = rowBase + ar;
            bool ok = (gr < M);
            const __half* src = A + (long long)(ok ? gr : 0) * 128 + ks + ac * 8;
            cpa16(&As[G3_AS(buf, ar, ac * 8)], src, ok);
        }
        // B chunk: 16 kpairs x 128 half2 = 8KB, 512 loads
#pragma unroll
        for (int l = 0; l < 2; l++) {
            int idx = tid + l * 256;
            int br = idx >> 5;
            int bc = (idx & 31) * 4;
            cpa16(&Bs[G3_BS(buf, br, bc)], B + br * 128 + bc, true);
        }
    };

    issue(0, 0);
    cpcommit();

#pragma unroll 1
    for (int c = 0; c < 12; c++) {
        if (c + 1 < 12) {
            issue(c + 1, (c + 1) & 1);
            cpcommit();
            cpwait<1>();
        } else {
            cpwait<0>();
        }
        __syncthreads();

        const int buf = c & 1;

#pragma unroll
        for (int kk = 0; kk < 2; kk++) {
            const int kb = kk * 16;   // half offset within chunk
            uint32_t a[2][4];
#pragma unroll
            for (int mf = 0; mf < 2; mf++) {
                int r0 = wm * 32 + mf * 16 + g;
                a[mf][0] = *reinterpret_cast<const uint32_t*>(&As[G3_AS(buf, r0, kb + 2 * t)]);
                a[mf][1] = *reinterpret_cast<const uint32_t*>(&As[G3_AS(buf, r0 + 8, kb + 2 * t)]);
                a[mf][2] = *reinterpret_cast<const uint32_t*>(&As[G3_AS(buf, r0, kb + 2 * t + 8)]);
                a[mf][3] = *reinterpret_cast<const uint32_t*>(&As[G3_AS(buf, r0 + 8, kb + 2 * t + 8)]);
            }
#pragma unroll
            for (int j = 0; j < 8; j++) {
                int n0 = wn * 64 + j * 8 + g;
                uint32_t b0 = *reinterpret_cast<const uint32_t*>(&Bs[G3_BS(buf, kk * 8 + t, n0)]);
                uint32_t b1 = *reinterpret_cast<const uint32_t*>(&Bs[G3_BS(buf, kk * 8 + t + 4, n0)]);
                mma_f16(acc[0][j], a[0][0], a[0][1], a[0][2], a[0][3], b0, b1);
                mma_f16(acc[1][j], a[1][0], a[1][1], a[1][2], a[1][3], b0, b1);
            }
        }
        __syncthreads();
    }

    if (donorm) {
        float ss[2][2] = { {0.f, 0.f}, {0.f, 0.f} };
#pragma unroll
        for (int mf = 0; mf < 2; mf++)
#pragma unroll
            for (int j = 0; j < 8; j++) {
                int n0 = wn * 64 + j * 8 + 2 * t;
                float b0 = sbias[n0], b1 = sbias[n0 + 1];
                float v0 = acc[mf][j][0] + b0; v0 = v0 > 0.f ? v0 : 0.f;
                float v1 = acc[mf][j][1] + b1; v1 = v1 > 0.f ? v1 : 0.f;
                float v2 = acc[mf][j][2] + b0; v2 = v2 > 0.f ? v2 : 0.f;
                float v3 = acc[mf][j][3] + b1; v3 = v3 > 0.f ? v3 : 0.f;
                acc[mf][j][0] = v0; acc[mf][j][1] = v1;
                acc[mf][j][2] = v2; acc[mf][j][3] = v3;
                ss[mf][0] = fmaf(v0, v0, fmaf(v1, v1, ss[mf][0]));
                ss[mf][1] = fmaf(v2, v2, fmaf(v3, v3, ss[mf][1]));
            }
#pragma unroll
        for (int mf = 0; mf < 2; mf++)
#pragma unroll
            for (int rp = 0; rp < 2; rp++) {
                float s = ss[mf][rp];
                s += __shfl_xor_sync(0xffffffffu, s, 1);
                s += __shfl_xor_sync(0xffffffffu, s, 2);
                ss[mf][rp] = s;
            }
        if (t == 0) {
#pragma unroll
            for (int mf = 0; mf < 2; mf++) {
                red[(wm * 32 + mf * 16 + g) * 2 + wn] = ss[mf][0];
                red[(wm * 32 + mf * 16 + g + 8) * 2 + wn] = ss[mf][1];
            }
        }
        __syncthreads();
#pragma unroll
        for (int mf = 0; mf < 2; mf++) {
            int r0 = wm * 32 + mf * 16 + g;
            float s0 = red[r0 * 2] + red[r0 * 2 + 1];
            float s1 = red[(r0 + 8) * 2] + red[(r0 + 8) * 2 + 1];
            float inv0 = 1.f / fmaxf(sqrtf(s0), 1e-12f);
            float inv1 = 1.f / fmaxf(sqrtf(s1), 1e-12f);
#pragma unroll
            for (int j = 0; j < 8; j++) {
                acc[mf][j][0] *= inv0; acc[mf][j][1] *= inv0;
                acc[mf][j][2] *= inv1; acc[mf][j][3] *= inv1;
            }
        }
    } else {
#pragma unroll
        for (int mf = 0; mf < 2; mf++)
#pragma unroll
            for (int j = 0; j < 8; j++) {
                int n0 = wn * 64 + j * 8 + 2 * t;
                float b0 = sbias[n0], b1 = sbias[n0 + 1];
                acc[mf][j][0] += b0; acc[mf][j][1] += b1;
                acc[mf][j][2] += b0; acc[mf][j][3] += b1;
            }
    }

    // stores: fp32 only when next aggregate needs it; fp16 always (gemm/readout)
#pragma unroll
    for (int mf = 0; mf < 2; mf++) {
        int r0 = rowBase + wm * 32 + mf * 16 + g;
        int r1 = r0 + 8;
#pragma unroll
        for (int j = 0; j < 8; j++) {
            int n0 = wn * 64 + j * 8 + 2 * t;
            if (r0 < M) {
                float2 v = make_float2(acc[mf][j][0], acc[mf][j][1]);
                if (donorm) *reinterpret_cast<float2*>(Cf + (long long)r0 * 128 + n0) = v;
                Ch[(long long)r0 * 64 + (n0 >> 1)] = __floats2half2_rn(v.x, v.y);
            }
            if (r1 < M) {
                float2 v = make_float2(acc[mf][j][2], acc[mf][j][3]);
                if (donorm) *reinterpret_cast<float2*>(Cf + (long long)r1 * 128 + n0) = v;
                Ch[(long long)r1 * 64 + (n0 >> 1)] = __floats2half2_rn(v.x, v.y);
            }
        }
    }
}

// ---------------- readout via fp16 MMA: out[M,64] = h @ W_ro + b_ro ----------
#define RO_AS(b, r, c) (((b) * 128 + (r)) * 40 + (c))      // halfs
#define RO_BS(b, k2, n) (((b) * 16 + (k2)) * 68 + (n))     // half2 units
#define ROH_SMEM_BYTES 29184
// layout: ROA halfs @0 (20480B), ROB half2 @20480 (8704B)

__global__ void __launch_bounds__(256) readout_mma_k(
    int xsel, const float* __restrict__ bro,
    float* __restrict__ out, int M) {

    extern __shared__ char smc[];
    __half* ROA = reinterpret_cast<__half*>(smc);
    __half2* ROB = reinterpret_cast<__half2*>(smc + 20480);

    const __half* A = (xsel == 0) ? g_xh1 : g_xh2;

    const int tid = threadIdx.x;
    const int wid = tid >> 5;
    const int lane = tid & 31;
    const int wm = wid & 3;
    const int wn = wid >> 2;
    const int g = lane >> 2;
    const int t = lane & 3;
    const int rowBase = blockIdx.x * 128;

    float acc[2][4][4];
#pragma unroll
    for (int i = 0; i < 2; i++)
#pragma unroll
        for (int j = 0; j < 4; j++)
#pragma unroll
            for (int q = 0; q < 4; q++) acc[i][j][q] = 0.f;

    auto issue = [&](int c, int buf) {
        const int ks = c * 32;   // halfs
#pragma unroll
        for (int l = 0; l < 2; l++) {
            int idx = tid + l * 256;
            int ar = idx >> 2;
            int ac = idx & 3;
            int gr = rowBase + ar;
            bool ok = (gr < M);
            const __half* src = A + (long long)(ok ? gr : 0) * 128 + ks + ac * 8;
            cpa16(&ROA[RO_AS(buf, ar, ac * 8)], src, ok);
        }
        // B chunk: 16 kpairs x 64 half2 = 4KB, 256 loads (1/thread)
        {
            int br = tid >> 4;
            int bc = (tid & 15) * 4;
            cpa16(&ROB[RO_BS(buf, br, bc)], g_wro2 + (c * 16 + br) * 64 + bc, true);
        }
    };

    issue(0, 0);
    cpcommit();

#pragma unroll 1
    for (int c = 0; c < 4; c++) {
        if (c + 1 < 4) {
            issue(c + 1, (c + 1) & 1);
            cpcommit();
            cpwait<1>();
        } else {
            cpwait<0>();
        }
        __syncthreads();

        const int buf = c & 1;

#pragma unroll
        for (int kk = 0; kk < 2; kk++) {
            const int kb = kk * 16;
            uint32_t a[2][4];
#pragma unroll
            for (int mf = 0; mf < 2; mf++) {
                int r0 = wm * 32 + mf * 16 + g;
                a[mf][0] = *reinterpret_cast<const uint32_t*>(&ROA[RO_AS(buf, r0, kb + 2 * t)]);
                a[mf][1] = *reinterpret_cast<const uint32_t*>(&ROA[RO_AS(buf, r0 + 8, kb + 2 * t)]);
                a[mf][2] = *reinterpret_cast<const uint32_t*>(&ROA[RO_AS(buf, r0, kb + 2 * t + 8)]);
                a[mf][3] = *reinterpret_cast<const uint32_t*>(&ROA[RO_AS(buf, r0 + 8, kb + 2 * t + 8)]);
            }
#pragma unroll
            for (int j = 0; j < 4; j++) {
                int n0 = wn * 32 + j * 8 + g;
                uint32_t b0 = *reinterpret_cast<const uint32_t*>(&ROB[RO_BS(buf, kk * 8 + t, n0)]);
                uint32_t b1 = *reinterpret_cast<const uint32_t*>(&ROB[RO_BS(buf, kk * 8 + t + 4, n0)]);
                mma_f16(acc[0][j], a[0][0], a[0][1], a[0][2], a[0][3], b0, b1);
                mma_f16(acc[1][j], a[1][0], a[1][1], a[1][2], a[1][3], b0, b1);
            }
        }
        __syncthreads();
    }

#pragma unroll
    for (int mf = 0; mf < 2; mf++) {
        int r0 = rowBase + wm * 32 + mf * 16 + g;
        int r1 = r0 + 8;
#pragma unroll
        for (int j = 0; j < 4; j++) {
            int n0 = wn * 32 + j * 8 + 2 * t;
            float b0 = bro[n0], b1 = bro[n0 + 1];
            if (r0 < M) {
                float2 v = make_float2(acc[mf][j][0] + b0, acc[mf][j][1] + b1);
                *reinterpret_cast<float2*>(out + (long long)r0 * 64 + n0) = v;
            }
            if (r1 < M) {
                float2 v = make_float2(acc[mf][j][2] + b0, acc[mf][j][3] + b1);
                *reinterpret_cast<float2*>(out + (long long)r1 * 64 + n0) = v;
            }
        }
    }
}

// ---------------- launch ----------------
extern "C" void kernel_launch(void* const* d_in, const int* in_sizes, int n_in,
                              void* d_out, int out_size) {
    const float* x          = (const float*)d_in[0];
    const int* ei           = (const int*)d_in[1];
    const float* theta      = (const float*)d_in[2];
    const float* Ws2d       = (const float*)d_in[3];
    const float* Wd2s       = (const float*)d_in[4];
    const float* Wself      = (const float*)d_in[5];
    const float* bs2d       = (const float*)d_in[6];
    const float* bd2s       = (const float*)d_in[7];
    const float* bself      = (const float*)d_in[8];
    const float* W_ro       = (const float*)d_in[9];
    const float* b_ro       = (const float*)d_in[10];
    float* out = (float*)d_out;

    int N = in_sizes[0] / 128;
    int E = in_sizes[2];
    int L = in_sizes[3] / (128 * 128);

    cudaFuncSetAttribute(gemm3_k, cudaFuncAttributeMaxDynamicSharedMemorySize,
                         GEMM3H_SMEM_BYTES);
    cudaFuncSetAttribute(readout_mma_k, cudaFuncAttributeMaxDynamicSharedMemorySize,
                         ROH_SMEM_BYTES);

    int nb = (N + SCAN_B - 1) / SCAN_B;
    long long prepCnt = (long long)N * 128;

    zero_wprep_k<<<(int)((prepCnt + 255) / 256), 256>>>(x, Ws2d, Wd2s, Wself, W_ro, N, L);
    edge_prep<<<(E + 255) / 256, 256>>>(ei, theta, E);
    scan1_k<<<nb, SCAN_B>>>(N);
    scan2_k<<<1, MAXNB>>>(nb);
    scan3_k<<<nb, SCAN_B>>>(N);
    norm_scatter_k<<<(E + 255) / 256, 256>>>(ei, theta, E);

    int gemmGrid = (N + 127) / 128;
    int aggGrid = (N * 32 + 255) / 256;

    for (int i = 0; i < L; i++) {
        int xsel = (i == 0) ? -1 : ((i - 1) & 1);
        int outsel = i & 1;
        aggregate_k<<<aggGrid, 256>>>(x, xsel, N);
        gemm3_k<<<gemmGrid, 256, GEMM3H_SMEM_BYTES>>>(
            xsel, i,
            bs2d + i * 128, bd2s + i * 128, bself + i * 128,
            outsel, N, (i != L - 1) ? 1 : 0);
    }
    readout_mma_k<<<gemmGrid, 256, ROH_SMEM_BYTES>>>((L - 1) & 1, b_ro, out, N);
}